// round 17
// baseline (speedup 1.0000x reference)
#include <cuda_runtime.h>
#include <cuda_bf16.h>

// Problem constants
#define C_DIM 3
#define H_DIM 32
#define W_DIM 32
#define Z_DIM 256
#define NTOK (128 * 1024)             // 131072 tokens
#define NBINS (C_DIM * H_DIM * W_DIM) // 3072 bins
#define CAP 192                       // max valid tokens per bin (mean ~21)
#define SCATBLKS 512                  // scatter blocks (64 thr x 4 tokens)
#define BIN0 SCATBLKS                 // first bin block id
#define PAD0 (SCATBLKS + NBINS)       // first pad block id
#define NPAD 2048                     // pad blocks (2 warps x 32 tokens each)
#define GRID (PAD0 + NPAD)
#define EPS 1e-6f
#define MAX_VAL 5.0f
#define MIN_VAL (-5.0f)

// mask: 32-bit word per token (bool promoted by harness); nonzero == padded.

// ---------------- device scratch (static; no allocations allowed) ----------
// All counters start zeroed (static init) and are self-reset every launch:
//   d_count[b]  -> reset by bin block b after reading
//   d_done/d_ack -> reset by the last bin block to pass the gate
__device__ int d_count[NBINS];
__device__ int d_tokenlist[NBINS * CAP];
__device__ int d_done;
__device__ int d_ack;

// ---------------- single fused kernel --------------------------------------
// blocks [0, SCATBLKS):    scatter valid token ids into per-bin slots,
//                          then release d_done (device-scope fence + atomic).
// blocks [BIN0, PAD0):     per-bin stats + normalize. Gate on d_done==SCATBLKS.
//                          64 threads; thread owns 4 features (float4).
// blocks [PAD0, GRID):     warp-per-32-token ballot scan; cooperative 1KB
//                          zero-fill per padded token. Independent.
__global__ __launch_bounds__(64) void k_all(
        const float* __restrict__ patches,
        const int* __restrict__ pc,
        const int* __restrict__ ph,
        const int* __restrict__ pw,
        const unsigned int* __restrict__ mask,
        const float* __restrict__ n_buf,
        const float* __restrict__ mean_in,
        const float* __restrict__ m2_in,
        float* __restrict__ out) {
    int tid = threadIdx.x;
    int bid = blockIdx.x;

    if (bid < SCATBLKS) {
        // ---- scatter path: 4 independent token chains per thread ----
        int base = bid * 256;
        #pragma unroll
        for (int j = 0; j < 4; j++) {
            int i = base + j * 64 + tid;
            if (mask[i] == 0u) {
                int flat = pc[i] * (H_DIM * W_DIM) + ph[i] * W_DIM + pw[i];
                int pos = atomicAdd(&d_count[flat], 1);
                if (pos < CAP) d_tokenlist[flat * CAP + pos] = i;
            }
        }
        __syncthreads();
        __threadfence();                       // release tokenlist/count writes
        if (tid == 0) atomicAdd(&d_done, 1);
        return;
    }

    if (bid >= PAD0) {
        // ---- pad-zero path ----
        int warp = (bid - PAD0) * 2 + (tid >> 5);   // global warp id
        int lane = tid & 31;
        int tok0 = warp * 32;                        // 32 tokens per warp
        unsigned int m = mask[tok0 + lane];
        unsigned int bal = __ballot_sync(0xFFFFFFFFu, m != 0u);
        float4 zero4 = make_float4(0.f, 0.f, 0.f, 0.f);
        float4* out4 = (float4*)out;
        while (bal) {
            int bit = __ffs(bal) - 1;
            bal &= bal - 1;
            long long rbase = (long long)(tok0 + bit) * 64; // 64 float4 per row
            out4[rbase + lane]      = zero4;
            out4[rbase + 32 + lane] = zero4;
        }
        return;
    }

    // ---- per-bin stats + normalize path ----
    int b = bid - BIN0;

    // gate: wait for all scatter blocks (they are ids [0,512) => wave-1 resident)
    if (tid == 0) {
        while (*(volatile int*)&d_done != SCATBLKS) __nanosleep(64);
        __threadfence();                       // acquire
    }
    __syncthreads();

    __shared__ int s_tok[CAP];
    int cnt_raw = d_count[b];
    int cnt = cnt_raw < CAP ? cnt_raw : CAP;
    for (int j = tid; j < cnt; j += 64) s_tok[j] = d_tokenlist[b * CAP + j];
    __syncthreads();
    if (tid == 0) {
        d_count[b] = 0;                        // self-zero for next replay
        int a = atomicAdd(&d_ack, 1);
        if (a == NBINS - 1) { d_done = 0; d_ack = 0; }  // last bin resets gate
    }

    const float4* patches4 = (const float4*)patches;
    float4*       out4     = (float4*)out;
    int idx = b * 64 + tid;                    // float4 index into stat rows
    float4 mo = ((const float4*)mean_in)[idx];

    float s1x = 0.f, s1y = 0.f, s1z = 0.f, s1w = 0.f;
    float s2x = 0.f, s2y = 0.f, s2z = 0.f, s2w = 0.f;

    int k = 0;
    for (; k + 3 < cnt; k += 4) {
        float4 p0 = patches4[s_tok[k + 0] * 64 + tid];
        float4 p1 = patches4[s_tok[k + 1] * 64 + tid];
        float4 p2 = patches4[s_tok[k + 2] * 64 + tid];
        float4 p3 = patches4[s_tok[k + 3] * 64 + tid];
        float e0x = p0.x - mo.x, e0y = p0.y - mo.y, e0z = p0.z - mo.z, e0w = p0.w - mo.w;
        float e1x = p1.x - mo.x, e1y = p1.y - mo.y, e1z = p1.z - mo.z, e1w = p1.w - mo.w;
        float e2x = p2.x - mo.x, e2y = p2.y - mo.y, e2z = p2.z - mo.z, e2w = p2.w - mo.w;
        float e3x = p3.x - mo.x, e3y = p3.y - mo.y, e3z = p3.z - mo.z, e3w = p3.w - mo.w;
        s1x += (e0x + e1x) + (e2x + e3x);
        s1y += (e0y + e1y) + (e2y + e3y);
        s1z += (e0z + e1z) + (e2z + e3z);
        s1w += (e0w + e1w) + (e2w + e3w);
        s2x += (e0x * e0x + e1x * e1x) + (e2x * e2x + e3x * e3x);
        s2y += (e0y * e0y + e1y * e1y) + (e2y * e2y + e3y * e3y);
        s2z += (e0z * e0z + e1z * e1z) + (e2z * e2z + e3z * e3z);
        s2w += (e0w * e0w + e1w * e1w) + (e2w * e2w + e3w * e3w);
    }
    for (; k < cnt; k++) {
        float4 p = patches4[s_tok[k] * 64 + tid];
        float ex = p.x - mo.x, ey = p.y - mo.y, ez = p.z - mo.z, ew = p.w - mo.w;
        s1x += ex; s1y += ey; s1z += ez; s1w += ew;
        s2x += ex * ex; s2y += ey * ey; s2z += ez * ez; s2w += ew * ew;
    }

    float n_new = n_buf[b] + (float)cnt_raw;
    float nden  = fmaxf(n_new, 1.0f);
    float rden  = 1.0f / nden;
    float dx = s1x * rden, dy = s1y * rden, dz = s1z * rden, dw = s1w * rden;
    float mnx = mo.x + dx, mny = mo.y + dy, mnz = mo.z + dz, mnw = mo.w + dw;
    float4 m2v = ((const float4*)m2_in)[idx];
    float m2x = m2v.x + (s2x - dx * s1x);
    float m2y = m2v.y + (s2y - dy * s1y);
    float m2z = m2v.z + (s2z - dz * s1z);
    float m2w = m2v.w + (s2w - dw * s1w);
    float varx = m2x * rden, vary = m2y * rden, varz = m2z * rden, varw = m2w * rden;
    if (n_new < 2.0f) { varx = 1.0f; vary = 1.0f; varz = 1.0f; varw = 1.0f; }
    float invx = 1.0f / (sqrtf(varx) + EPS);
    float invy = 1.0f / (sqrtf(vary) + EPS);
    float invz = 1.0f / (sqrtf(varz) + EPS);
    float invw = 1.0f / (sqrtf(varw) + EPS);

    // pass 2: normalize (re-read is L2-hot) and write out
    k = 0;
    for (; k + 1 < cnt; k += 2) {
        int t0 = s_tok[k + 0], t1 = s_tok[k + 1];
        float4 p0 = patches4[t0 * 64 + tid];
        float4 p1 = patches4[t1 * 64 + tid];
        float4 r0, r1;
        r0.x = fminf(fmaxf((p0.x - mnx) * invx, MIN_VAL), MAX_VAL);
        r0.y = fminf(fmaxf((p0.y - mny) * invy, MIN_VAL), MAX_VAL);
        r0.z = fminf(fmaxf((p0.z - mnz) * invz, MIN_VAL), MAX_VAL);
        r0.w = fminf(fmaxf((p0.w - mnw) * invw, MIN_VAL), MAX_VAL);
        r1.x = fminf(fmaxf((p1.x - mnx) * invx, MIN_VAL), MAX_VAL);
        r1.y = fminf(fmaxf((p1.y - mny) * invy, MIN_VAL), MAX_VAL);
        r1.z = fminf(fmaxf((p1.z - mnz) * invz, MIN_VAL), MAX_VAL);
        r1.w = fminf(fmaxf((p1.w - mnw) * invw, MIN_VAL), MAX_VAL);
        out4[t0 * 64 + tid] = r0;
        out4[t1 * 64 + tid] = r1;
    }
    for (; k < cnt; k++) {
        int t0 = s_tok[k];
        float4 p = patches4[t0 * 64 + tid];
        float4 r;
        r.x = fminf(fmaxf((p.x - mnx) * invx, MIN_VAL), MAX_VAL);
        r.y = fminf(fmaxf((p.y - mny) * invy, MIN_VAL), MAX_VAL);
        r.z = fminf(fmaxf((p.z - mnz) * invz, MIN_VAL), MAX_VAL);
        r.w = fminf(fmaxf((p.w - mnw) * invw, MIN_VAL), MAX_VAL);
        out4[t0 * 64 + tid] = r;
    }
}

// ---------------- launch ----------------------------------------------------
extern "C" void kernel_launch(void* const* d_in, const int* in_sizes, int n_in,
                              void* d_out, int out_size) {
    const float*        patches = (const float*)d_in[0];
    const int*          pc      = (const int*)d_in[1];
    const int*          ph      = (const int*)d_in[2];
    const int*          pw      = (const int*)d_in[3];
    const unsigned int* mask    = (const unsigned int*)d_in[4];
    const float*        n_buf   = (const float*)d_in[5];
    const float*        mean_in = (const float*)d_in[6];
    const float*        m2_in   = (const float*)d_in[7];
    float*              out     = (float*)d_out;

    k_all<<<GRID, 64>>>(patches, pc, ph, pw, mask, n_buf, mean_in, m2_in, out);
}